// round 11
// baseline (speedup 1.0000x reference)
#include <cuda_runtime.h>
#include <cstdint>

#define B_     2
#define NRES   2048
#define NATOM  16384
#define CS     384
#define COUT   50
#define OPAD   64
#define KT     64
#define RPB    16                          // rows per GEMM block
#define GEMM_BLOCKS ((B_ * NRES) / RPB)    // 256
#define SG_BLOCKS   ((B_ * NATOM) / 8)     // 4096 (1 atom/warp, 8 warps/block)

// Scratch
__device__ float g_res_logits[B_ * NRES * COUT];   // 3.2 MB (L2-resident)

// ---------------------------------------------------------------------------
// Kernel 1: res_logits = s @ W^T + b.
// 256 blocks x 16 rows, thread microtile 1 row x 4 outs. W transposed per
// K-tile into smem (lanes stride o -> conflict-free STS).
// ---------------------------------------------------------------------------
__global__ void __launch_bounds__(256)
gemm_kernel(const float* __restrict__ s,     // [B, NRES, CS]
            const float* __restrict__ W,     // [COUT, CS]
            const float* __restrict__ bias)  // [COUT]
{
    __shared__ float s_sm[RPB][KT];     // 4 KB
    __shared__ float wt_sm[KT][OPAD];   // 16 KB

    const int tid = threadIdx.x;
    const int to  = tid & 15;           // o-group: o0 = 4*to
    const int tr  = tid >> 4;           // row 0..15
    const int o0  = to << 2;
    const int row0 = blockIdx.x * RPB;

    const int wo = tid & 63;            // out channel for W transpose loads
    const int wg = tid >> 6;            // k-group 0..3

    float4 acc = make_float4(0.f, 0.f, 0.f, 0.f);

    for (int kt = 0; kt < CS; kt += KT) {
        {   // s tile: 16 rows x 64 k = 256 float4, 1 per thread (coalesced)
            const float4* __restrict__ sg = reinterpret_cast<const float4*>(s);
            const int r = tid >> 4;
            const int c = tid & 15;
            reinterpret_cast<float4*>(&s_sm[0][0])[tid] =
                sg[(size_t)(row0 + r) * (CS / 4) + (kt >> 2) + c];
        }
        // W tile transposed in-smem
        #pragma unroll
        for (int m = 0; m < 4; ++m) {
            const int k0 = (wg << 4) + (m << 2);
            float4 v = make_float4(0.f, 0.f, 0.f, 0.f);
            if (wo < COUT)
                v = *reinterpret_cast<const float4*>(&W[(size_t)wo * CS + kt + k0]);
            wt_sm[k0 + 0][wo] = v.x;
            wt_sm[k0 + 1][wo] = v.y;
            wt_sm[k0 + 2][wo] = v.z;
            wt_sm[k0 + 3][wo] = v.w;
        }
        __syncthreads();

        #pragma unroll
        for (int kk = 0; kk < KT; kk += 4) {
            const float4 sa = *reinterpret_cast<const float4*>(&s_sm[tr][kk]);
            const float4 w0 = *reinterpret_cast<const float4*>(&wt_sm[kk + 0][o0]);
            const float4 w1 = *reinterpret_cast<const float4*>(&wt_sm[kk + 1][o0]);
            const float4 w2 = *reinterpret_cast<const float4*>(&wt_sm[kk + 2][o0]);
            const float4 w3 = *reinterpret_cast<const float4*>(&wt_sm[kk + 3][o0]);

            acc.x = fmaf(sa.x, w0.x, acc.x); acc.y = fmaf(sa.x, w0.y, acc.y);
            acc.z = fmaf(sa.x, w0.z, acc.z); acc.w = fmaf(sa.x, w0.w, acc.w);
            acc.x = fmaf(sa.y, w1.x, acc.x); acc.y = fmaf(sa.y, w1.y, acc.y);
            acc.z = fmaf(sa.y, w1.z, acc.z); acc.w = fmaf(sa.y, w1.w, acc.w);
            acc.x = fmaf(sa.z, w2.x, acc.x); acc.y = fmaf(sa.z, w2.y, acc.y);
            acc.z = fmaf(sa.z, w2.z, acc.z); acc.w = fmaf(sa.z, w2.w, acc.w);
            acc.x = fmaf(sa.w, w3.x, acc.x); acc.y = fmaf(sa.w, w3.y, acc.y);
            acc.z = fmaf(sa.w, w3.z, acc.z); acc.w = fmaf(sa.w, w3.w, acc.w);
        }
        __syncthreads();
    }

    const float a4[4] = {acc.x, acc.y, acc.z, acc.w};
    #pragma unroll
    for (int c = 0; c < 4; ++c) {
        const int o = o0 + c;
        if (o < COUT)
            g_res_logits[(size_t)(row0 + tr) * COUT + o] = a4[c] + bias[o];
    }
}

// ---------------------------------------------------------------------------
// Kernel 2 (R6-proven, 29.9us measured): warp per atom. Scan one-hot row
// (512-float rounds, 4x LDG.128 in flight), ballot early-exit, then gather
// 50 floats directly to out. res_logits complete (separate launch).
// ---------------------------------------------------------------------------
__global__ void __launch_bounds__(256)
scan_gather_kernel(const float* __restrict__ tta,   // [B, NATOM, NRES]
                   float* __restrict__ out)         // [B, NATOM, COUT]
{
    const int gwarp = (blockIdx.x * blockDim.x + threadIdx.x) >> 5;
    const int lane  = threadIdx.x & 31;

    const float4* __restrict__ row =
        reinterpret_cast<const float4*>(tta + (size_t)gwarp * NRES);

    int idx = 0;
    // 512 float4 per row; rounds of 128 float4 (512 floats), MLP=4 LDG.128
    #pragma unroll 1
    for (int r = 0; r < 4; ++r) {
        float4 v[4];
        #pragma unroll
        for (int j = 0; j < 4; ++j)
            v[j] = __ldcs(&row[r * 128 + j * 32 + lane]);

        int my = -1;
        #pragma unroll
        for (int j = 3; j >= 0; --j) {
            const int jb = (r * 128 + j * 32 + lane) << 2;
            if (v[j].w != 0.0f) my = jb + 3;
            if (v[j].z != 0.0f) my = jb + 2;
            if (v[j].y != 0.0f) my = jb + 1;
            if (v[j].x != 0.0f) my = jb;
        }

        const unsigned m = __ballot_sync(0xffffffffu, my >= 0);
        if (m) {
            idx = __shfl_sync(0xffffffffu, my, __ffs(m) - 1);
            break;
        }
    }

    // Immediate gather: 25 lanes x float2 = 200 B (res_logits is L2-resident).
    const int b = gwarp >> 14;
    const float2* __restrict__ src = reinterpret_cast<const float2*>(
        g_res_logits + ((size_t)b * NRES + idx) * COUT);
    float2* __restrict__ dst = reinterpret_cast<float2*>(
        out + (size_t)gwarp * COUT);
    if (lane < COUT / 2) dst[lane] = src[lane];
}

extern "C" void kernel_launch(void* const* d_in, const int* in_sizes, int n_in,
                              void* d_out, int out_size)
{
    const float* s    = (const float*)d_in[0];  // [B, NRES, CS]
    const float* tta  = (const float*)d_in[1];  // [B, NATOM, NRES]
    const float* W    = (const float*)d_in[2];  // [COUT, CS]
    const float* bias = (const float*)d_in[3];  // [COUT]
    float* out = (float*)d_out;

    (void)in_sizes; (void)n_in; (void)out_size;

    gemm_kernel<<<GEMM_BLOCKS, 256>>>(s, W, bias);
    scan_gather_kernel<<<SG_BLOCKS, 256>>>(tta, out);
}

// round 12
// speedup vs baseline: 1.4642x; 1.4642x over previous
#include <cuda_runtime.h>
#include <cstdint>

#define B_     2
#define NRES   2048
#define NATOM  16384
#define CS     384
#define COUT   50
#define OPAD   64
#define KT     64
#define RPB    32
#define GEMM_BLOCKS ((B_ * NRES) / RPB)   // 128
#define SCAN_BLOCKS ((B_ * NATOM) / 8)    // 4096 (1 atom/warp, 8 warps/block)

// Scratch
__device__ float g_res_logits[B_ * NRES * COUT];   // 3.2 MB (L2-resident)
__device__ int   g_idx[B_ * NATOM];                // 128 KB

// ---------------------------------------------------------------------------
// Fused kernel (R9-proven ~29us): no inter-block sync.
//   blocks [0, 128):    GEMM res_logits = s @ W^T + b  (hidden under scan)
//   blocks [128, 4224): warp-per-atom one-hot scan, 512-float rounds
//                       (MLP = 4x LDG.128), ballot early-exit -> g_idx
// ---------------------------------------------------------------------------
__global__ void __launch_bounds__(256)
fused_kernel(const float* __restrict__ s,     // [B, NRES, CS]
             const float* __restrict__ tta,   // [B, NATOM, NRES]
             const float* __restrict__ W,     // [COUT, CS]
             const float* __restrict__ bias)  // [COUT]
{
    __shared__ float s_sm[RPB][KT];     // 8 KB
    __shared__ float wt_sm[KT][OPAD];   // 16 KB

    const int tid = threadIdx.x;

    if (blockIdx.x < GEMM_BLOCKS) {
        // ----------------- GEMM branch -----------------
        const int to  = tid & 15;
        const int tr  = tid >> 4;
        const int o0  = to << 2;
        const int r0  = tr << 1;
        const int r1  = r0 + 1;
        const int row0 = blockIdx.x * RPB;

        const int wo = tid & 63;
        const int wg = tid >> 6;

        float4 accA = make_float4(0.f, 0.f, 0.f, 0.f);
        float4 accB = make_float4(0.f, 0.f, 0.f, 0.f);

        for (int kt = 0; kt < CS; kt += KT) {
            {
                const float4* __restrict__ sg = reinterpret_cast<const float4*>(s);
                float4* s4 = reinterpret_cast<float4*>(&s_sm[0][0]);
                #pragma unroll
                for (int i = 0; i < 2; ++i) {
                    const int f = tid + 256 * i;
                    const int r = f >> 4;
                    const int c = f & 15;
                    s4[f] = sg[(size_t)(row0 + r) * (CS / 4) + (kt >> 2) + c];
                }
            }
            #pragma unroll
            for (int m = 0; m < 4; ++m) {
                const int k0 = (wg << 4) + (m << 2);
                float4 v = make_float4(0.f, 0.f, 0.f, 0.f);
                if (wo < COUT)
                    v = *reinterpret_cast<const float4*>(&W[(size_t)wo * CS + kt + k0]);
                wt_sm[k0 + 0][wo] = v.x;
                wt_sm[k0 + 1][wo] = v.y;
                wt_sm[k0 + 2][wo] = v.z;
                wt_sm[k0 + 3][wo] = v.w;
            }
            __syncthreads();

            #pragma unroll
            for (int kk = 0; kk < KT; kk += 4) {
                const float4 sa = *reinterpret_cast<const float4*>(&s_sm[r0][kk]);
                const float4 sb = *reinterpret_cast<const float4*>(&s_sm[r1][kk]);
                const float4 w0 = *reinterpret_cast<const float4*>(&wt_sm[kk + 0][o0]);
                const float4 w1 = *reinterpret_cast<const float4*>(&wt_sm[kk + 1][o0]);
                const float4 w2 = *reinterpret_cast<const float4*>(&wt_sm[kk + 2][o0]);
                const float4 w3 = *reinterpret_cast<const float4*>(&wt_sm[kk + 3][o0]);

                accA.x = fmaf(sa.x, w0.x, accA.x); accA.y = fmaf(sa.x, w0.y, accA.y);
                accA.z = fmaf(sa.x, w0.z, accA.z); accA.w = fmaf(sa.x, w0.w, accA.w);
                accB.x = fmaf(sb.x, w0.x, accB.x); accB.y = fmaf(sb.x, w0.y, accB.y);
                accB.z = fmaf(sb.x, w0.z, accB.z); accB.w = fmaf(sb.x, w0.w, accB.w);

                accA.x = fmaf(sa.y, w1.x, accA.x); accA.y = fmaf(sa.y, w1.y, accA.y);
                accA.z = fmaf(sa.y, w1.z, accA.z); accA.w = fmaf(sa.y, w1.w, accA.w);
                accB.x = fmaf(sb.y, w1.x, accB.x); accB.y = fmaf(sb.y, w1.y, accB.y);
                accB.z = fmaf(sb.y, w1.z, accB.z); accB.w = fmaf(sb.y, w1.w, accB.w);

                accA.x = fmaf(sa.z, w2.x, accA.x); accA.y = fmaf(sa.z, w2.y, accA.y);
                accA.z = fmaf(sa.z, w2.z, accA.z); accA.w = fmaf(sa.z, w2.w, accA.w);
                accB.x = fmaf(sb.z, w2.x, accB.x); accB.y = fmaf(sb.z, w2.y, accB.y);
                accB.z = fmaf(sb.z, w2.z, accB.z); accB.w = fmaf(sb.z, w2.w, accB.w);

                accA.x = fmaf(sa.w, w3.x, accA.x); accA.y = fmaf(sa.w, w3.y, accA.y);
                accA.z = fmaf(sa.w, w3.z, accA.z); accA.w = fmaf(sa.w, w3.w, accA.w);
                accB.x = fmaf(sb.w, w3.x, accB.x); accB.y = fmaf(sb.w, w3.y, accB.y);
                accB.z = fmaf(sb.w, w3.z, accB.z); accB.w = fmaf(sb.w, w3.w, accB.w);
            }
            __syncthreads();
        }

        const float aA[4] = {accA.x, accA.y, accA.z, accA.w};
        const float aB[4] = {accB.x, accB.y, accB.z, accB.w};
        #pragma unroll
        for (int c = 0; c < 4; ++c) {
            const int o = o0 + c;
            if (o < COUT) {
                const float bv = bias[o];
                g_res_logits[(size_t)(row0 + r0) * COUT + o] = aA[c] + bv;
                g_res_logits[(size_t)(row0 + r1) * COUT + o] = aB[c] + bv;
            }
        }
    } else {
        // -------- scan branch: 1 atom/warp, 512-float rounds, MLP=4 --------
        const int gwarp = (blockIdx.x - GEMM_BLOCKS) * 8 + (tid >> 5);
        const int lane  = tid & 31;

        const float4* __restrict__ row =
            reinterpret_cast<const float4*>(tta + (size_t)gwarp * NRES);

        int idx = 0;
        #pragma unroll 1
        for (int r = 0; r < 4; ++r) {
            float4 v[4];
            #pragma unroll
            for (int j = 0; j < 4; ++j)
                v[j] = __ldcs(&row[r * 128 + j * 32 + lane]);

            int my = -1;
            #pragma unroll
            for (int j = 3; j >= 0; --j) {
                const int jb = (r * 128 + j * 32 + lane) << 2;
                if (v[j].w != 0.0f) my = jb + 3;
                if (v[j].z != 0.0f) my = jb + 2;
                if (v[j].y != 0.0f) my = jb + 1;
                if (v[j].x != 0.0f) my = jb;
            }

            const unsigned m = __ballot_sync(0xffffffffu, my >= 0);
            if (m) {
                idx = __shfl_sync(0xffffffffu, my, __ffs(m) - 1);
                break;
            }
        }

        if (lane == 0) g_idx[gwarp] = idx;
    }
}

// ---------------------------------------------------------------------------
// Gather (PDL secondary): 8 atoms/warp. cudaGridDependencySynchronize() makes
// all fused_kernel writes visible before any consumption; the block launch &
// preamble overlap the fused kernel's tail.
// ---------------------------------------------------------------------------
__global__ void __launch_bounds__(256)
gather_kernel(float* __restrict__ out)
{
#if __CUDA_ARCH__ >= 900
    cudaGridDependencySynchronize();
#endif

    const int gw   = (blockIdx.x * blockDim.x + threadIdx.x) >> 5;
    const int lane = threadIdx.x & 31;
    const int a0   = gw * 8;                 // 8 consecutive atoms

    int myv = 0;
    if (lane < 8) myv = g_idx[a0 + lane];

    const int b = a0 >> 14;                  // uniform across the 8 atoms
    const float* __restrict__ base = g_res_logits + (size_t)b * NRES * COUT;

    const float2* src[8];
    #pragma unroll
    for (int j = 0; j < 8; ++j) {
        const int ij = __shfl_sync(0xffffffffu, myv, j);
        src[j] = reinterpret_cast<const float2*>(base + (size_t)ij * COUT);
    }

    if (lane < COUT / 2) {
        float2 x[8];
        #pragma unroll
        for (int j = 0; j < 8; ++j)          // 8 independent L2 loads
            x[j] = src[j][lane];
        float2* __restrict__ d = reinterpret_cast<float2*>(out + (size_t)a0 * COUT);
        #pragma unroll
        for (int j = 0; j < 8; ++j)          // 8 coalesced 200 B stores
            d[lane + 25 * j] = x[j];
    }
}

extern "C" void kernel_launch(void* const* d_in, const int* in_sizes, int n_in,
                              void* d_out, int out_size)
{
    const float* s    = (const float*)d_in[0];  // [B, NRES, CS]
    const float* tta  = (const float*)d_in[1];  // [B, NATOM, NRES]
    const float* W    = (const float*)d_in[2];  // [COUT, CS]
    const float* bias = (const float*)d_in[3];  // [COUT]
    float* out = (float*)d_out;

    (void)in_sizes; (void)n_in; (void)out_size;

    fused_kernel<<<GEMM_BLOCKS + SCAN_BLOCKS, 256>>>(s, tta, W, bias);

    // PDL launch of the gather: overlaps launch/preamble with fused_kernel's
    // tail; cudaGridDependencySynchronize() inside provides the ordering.
    cudaLaunchConfig_t cfg = {};
    cfg.gridDim       = dim3(512, 1, 1);     // 32768 atoms / 8 per warp / 8 warps
    cfg.blockDim      = dim3(256, 1, 1);
    cfg.dynamicSmemBytes = 0;
    cfg.stream        = 0;                   // same (capture) stream

    cudaLaunchAttribute attrs[1];
    attrs[0].id = cudaLaunchAttributeProgrammaticStreamSerialization;
    attrs[0].val.programmaticStreamSerializationAllowed = 1;
    cfg.attrs    = attrs;
    cfg.numAttrs = 1;

    cudaLaunchKernelEx(&cfg, gather_kernel, out);
}